// round 15
// baseline (speedup 1.0000x reference)
#include <cuda_runtime.h>
#include <stdint.h>

#define NN      100000
#define F       128
#define KNBR    64
#define SCAP    80
#define TCAP    4096
#define EMAX    3300000
#define NWORDS  ((NN + 31) / 32)
#define TILE16  16
#define HTILE   8

// dynamic smem sizes (bytes)
#define SMEM_H    (2 * F * F * 4 + F * 36 * 4)   // k_h: interleaved W + staging
#define SMEM_EMB  (2 * F * F * 4 + F * 20 * 4)   // k_emb: Wl + Wr + staging
#define SMEM_HEAD (3 * F * F * 4)                 // k_head2: Wlin1

// ---------------- static scratch (no allocations allowed) ----------------
__device__ unsigned g_bitS[NWORDS];
__device__ unsigned g_bitT[NWORDS];
__device__ int   g_idxS[NN];
__device__ int   g_idxT[NN];
__device__ int   g_sNodes[SCAP];
__device__ int   g_tNodes[TCAP];
__device__ int   g_sCount;
__device__ int   g_tCount;
__device__ int   g_e2Count;
__device__ int   g_edge64;
__device__ int   g_nbr64;
__device__ int   g_e2src[EMAX];
__device__ int   g_e2dst[EMAX];
__device__ float g_agg1[(size_t)TCAP * F];
__device__ int   g_cnt1[TCAP];
__device__ float g_h[(size_t)TCAP * F];
__device__ float g_agg2[SCAP * F];
__device__ int   g_cnt2[SCAP];
__device__ float g_emb[SCAP * F];

__device__ __forceinline__ int read_scalar_idx(const void* p) {
    int v = *(const int*)p;
    if (v >= 0 && v < NN) return v;
    float f = *(const float*)p;
    return (int)f;
}

__device__ __forceinline__ void claimT(int node) {
    unsigned m = 1u << (node & 31);
    unsigned old = atomicOr(&g_bitT[node >> 5], m);
    if (!(old & m)) {
        int ts = atomicAdd(&g_tCount, 1);
        if (ts < TCAP) { g_tNodes[ts] = node; g_idxT[node] = ts; }
        else g_idxT[node] = 0;
    }
}

// ---------- kernel 1 (1 block): bitmaps + counters + dtype probes + build S ----------
__global__ void k_prepS(const void* edges, const void* nbrs,
                        const void* curr_p, const void* dest_p, long long E) {
    int t = threadIdx.x;
    for (int i = t; i < NWORDS; i += blockDim.x) { g_bitS[i] = 0u; g_bitT[i] = 0u; }
    if (t == 0) {
        g_sCount = 0; g_tCount = 0; g_e2Count = 0;
        const long long* e64 = (const long long*)edges;
        int n = (int)(2 * E < 8 ? 2 * E : 8);
        int ok = 1;
        for (int q = 0; q < n; q++) {
            long long v = e64[q];
            if (v < 0 || v >= NN) ok = 0;
        }
        g_edge64 = ok;
        const long long* n64 = (const long long*)nbrs;
        ok = 1;
        for (int q = 0; q < 8; q++) {
            long long v = n64[q];
            if (v < 0 || v >= NN) ok = 0;
        }
        g_nbr64 = ok;
    }
    __syncthreads();
    if (t < KNBR + 2) {
        int node;
        if (t == 0)      node = read_scalar_idx(curr_p);
        else if (t == 1) node = read_scalar_idx(dest_p);
        else node = g_nbr64 ? (int)((const long long*)nbrs)[t - 2]
                            : ((const int*)nbrs)[t - 2];
        if (node >= 0 && node < NN) {
            unsigned m = 1u << (node & 31);
            unsigned old = atomicOr(&g_bitS[node >> 5], m);
            if (!(old & m)) {
                int s = atomicAdd(&g_sCount, 1);
                if (s < SCAP) { g_sNodes[s] = node; g_idxS[node] = s; }
            }
            claimT(node);
        }
    }
}

// ---------- kernel 2: zero accum slices + scan edges (4/thread), dst in S ----------
__global__ void k_scan1(const void* __restrict__ edges, long long E) {
    {
        long long gt = (long long)blockIdx.x * blockDim.x + threadIdx.x;
        long long gs = (long long)gridDim.x * blockDim.x;
        for (long long i = gt; i < (long long)TCAP * F; i += gs) g_agg1[i] = 0.0f;
        for (long long i = gt; i < TCAP; i += gs) g_cnt1[i] = 0;
        for (long long i = gt; i < SCAP * F; i += gs) g_agg2[i] = 0.0f;
        if (gt < SCAP) g_cnt2[gt] = 0;
    }
    long long base = ((long long)blockIdx.x * blockDim.x + threadIdx.x) * 4;
    if (base >= E) return;
    int is64 = g_edge64;
    int nv = (int)(E - base < 4 ? E - base : 4);
    bool vec = (nv == 4);
    int d[4];
    if (is64) {
        const long long* __restrict__ p = (const long long*)edges + E + base;
        if (vec) {
            longlong2 v0 = *(const longlong2*)p;
            longlong2 v1 = *(const longlong2*)(p + 2);
            d[0] = (int)v0.x; d[1] = (int)v0.y; d[2] = (int)v1.x; d[3] = (int)v1.y;
        } else {
            #pragma unroll
            for (int q = 0; q < 4; q++) d[q] = (q < nv) ? (int)p[q] : -1;
        }
    } else {
        const int* __restrict__ p = (const int*)edges + E + base;
        if (vec) {
            int4 v = *(const int4*)p;
            d[0] = v.x; d[1] = v.y; d[2] = v.z; d[3] = v.w;
        } else {
            #pragma unroll
            for (int q = 0; q < 4; q++) d[q] = (q < nv) ? p[q] : -1;
        }
    }
    #pragma unroll
    for (int q = 0; q < 4; q++) {
        int dd = d[q];
        if ((unsigned)dd < NN && (g_bitS[dd >> 5] & (1u << (dd & 31)))) {
            int ss = g_idxS[dd];
            int s = is64 ? (int)((const long long*)edges)[base + q]
                         : ((const int*)edges)[base + q];
            if ((unsigned)s >= NN) continue;
            atomicAdd(&g_cnt2[ss], 1);
            int pos = atomicAdd(&g_e2Count, 1);
            if (pos < EMAX) { g_e2src[pos] = s; g_e2dst[pos] = ss; }
            claimT(s);
        }
    }
}

// ---------- kernel 3: scan edges (4/thread), dst in T -> warp-coop accumulate x[src] ----------
__global__ void k_scan2(const void* __restrict__ edges, const float* __restrict__ x,
                        long long E) {
    long long base = ((long long)blockIdx.x * blockDim.x + threadIdx.x) * 4;
    int lane = threadIdx.x & 31;
    int is64 = g_edge64;
    int d[4] = {-1, -1, -1, -1};
    if (base < E) {
        int nv = (int)(E - base < 4 ? E - base : 4);
        bool vec = (nv == 4);
        if (is64) {
            const long long* __restrict__ p = (const long long*)edges + E + base;
            if (vec) {
                longlong2 v0 = *(const longlong2*)p;
                longlong2 v1 = *(const longlong2*)(p + 2);
                d[0] = (int)v0.x; d[1] = (int)v0.y; d[2] = (int)v1.x; d[3] = (int)v1.y;
            } else {
                #pragma unroll
                for (int q = 0; q < 4; q++) if (q < nv) d[q] = (int)p[q];
            }
        } else {
            const int* __restrict__ p = (const int*)edges + E + base;
            if (vec) {
                int4 v = *(const int4*)p;
                d[0] = v.x; d[1] = v.y; d[2] = v.z; d[3] = v.w;
            } else {
                #pragma unroll
                for (int q = 0; q < 4; q++) if (q < nv) d[q] = p[q];
            }
        }
    }
    int s[4], ts[4];
    bool act[4];
    #pragma unroll
    for (int q = 0; q < 4; q++) {
        act[q] = false;
        s[q] = 0; ts[q] = 0;
        int dd = d[q];
        if ((unsigned)dd < NN && (g_bitT[dd >> 5] & (1u << (dd & 31)))) {
            ts[q] = g_idxT[dd];
            int sv = is64 ? (int)((const long long*)edges)[base + q]
                          : ((const int*)edges)[base + q];
            if ((unsigned)sv < NN) {
                s[q] = sv;
                atomicAdd(&g_cnt1[ts[q]], 1);
                act[q] = true;
            }
        }
    }
    #pragma unroll
    for (int q = 0; q < 4; q++) {
        unsigned m = __ballot_sync(0xffffffffu, act[q]);
        while (m) {
            int l = __ffs(m) - 1;
            m &= m - 1;
            int ls = __shfl_sync(0xffffffffu, s[q], l);
            int lt = __shfl_sync(0xffffffffu, ts[q], l);
            float4 v = ((const float4*)(x + (size_t)ls * F))[lane];
            float* dp = &g_agg1[(size_t)lt * F + lane * 4];
            asm volatile("red.global.add.v4.f32 [%0], {%1,%2,%3,%4};"
                         :: "l"(dp), "f"(v.x), "f"(v.y), "f"(v.z), "f"(v.w) : "memory");
        }
    }
}

// ---------- kernel 4: h = relu(mean1 @ W1l + b1 + x @ W1r), 16-node tiles ----------
// 512 threads; interleaved weights; software-pipelined inner loop with
// 8 independent FMA chains (split x/y) to cover LDS latency at 16 warps/SM.
__global__ void __launch_bounds__(512, 1) k_h(
                    const float* __restrict__ x,
                    const float* __restrict__ Wl, const float* __restrict__ Wr,
                    const float* __restrict__ b) {
    extern __shared__ float smem[];
    float* sW  = smem;                  // 2*F*F interleaved {wl,wr}
    float* stg = smem + 2 * F * F;      // F*36
    int tid = threadIdx.x;
    int tc = g_tCount; if (tc > TCAP) tc = TCAP;
    int ntiles = (tc + TILE16 - 1) / TILE16;
    if ((int)blockIdx.x >= ntiles) return;
    {
        const float4* wl4 = (const float4*)Wl;
        const float4* wr4 = (const float4*)Wr;
        float2* sW2 = (float2*)sW;
        #pragma unroll
        for (int i = tid; i < F * F / 4; i += 512) {
            float4 a = wl4[i];
            float4 c = wr4[i];
            sW2[4 * i + 0] = make_float2(a.x, c.x);
            sW2[4 * i + 1] = make_float2(a.y, c.y);
            sW2[4 * i + 2] = make_float2(a.z, c.z);
            sW2[4 * i + 3] = make_float2(a.w, c.w);
        }
    }
    __syncthreads();
    int j       = tid & 127;
    int quarter = tid >> 7;
    for (int tile = blockIdx.x; tile < ntiles; tile += gridDim.x) {
        int g0 = tile * TILE16;
        int nvalid = min(TILE16, tc - g0);
        #pragma unroll
        for (int qi = 0; qi < 4; qi++) {
            int q = quarter * 4 + qi;
            float mv = 0.0f, xv = 0.0f;
            if (q < nvalid) {
                int t = g0 + q;
                int node = g_tNodes[t];
                float inv = 1.0f / (float)max(g_cnt1[t], 1);
                mv = g_agg1[(size_t)t * F + j] * inv;
                xv = x[(size_t)node * F + j];
            }
            stg[j * 36 + 2 * q]     = mv;
            stg[j * 36 + 2 * q + 1] = xv;
        }
        __syncthreads();
        // 8 independent accumulator chains
        float a0x = 0.f, a0y = 0.f, a1x = 0.f, a1y = 0.f;
        float a2x = 0.f, a2y = 0.f, a3x = 0.f, a3y = 0.f;
        // software pipeline: prefetch k+1 while computing k
        float2 w = ((const float2*)&sW[0])[j];
        {
            const float4* r = (const float4*)&stg[quarter * 8];
            float4 v0 = r[0], v1 = r[1];
            #pragma unroll 8
            for (int k = 0; k < F; k++) {
                float2 wn;
                float4 v0n, v1n;
                if (k + 1 < F) {
                    wn = ((const float2*)&sW[(k + 1) * 256])[j];
                    const float4* rn = (const float4*)&stg[(k + 1) * 36 + quarter * 8];
                    v0n = rn[0];
                    v1n = rn[1];
                } else {
                    wn = w; v0n = v0; v1n = v1;
                }
                a0x += v0.x * w.x;  a0y += v0.y * w.y;
                a1x += v0.z * w.x;  a1y += v0.w * w.y;
                a2x += v1.x * w.x;  a2y += v1.y * w.y;
                a3x += v1.z * w.x;  a3y += v1.w * w.y;
                w = wn; v0 = v0n; v1 = v1n;
            }
        }
        float bb = b[j];
        float acc[4] = {a0x + a0y, a1x + a1y, a2x + a2y, a3x + a3y};
        #pragma unroll
        for (int qi = 0; qi < 4; qi++) {
            int q = quarter * 4 + qi;
            if (q < nvalid)
                g_h[(size_t)(g0 + q) * F + j] = fmaxf(acc[qi] + bb, 0.0f);
        }
        __syncthreads();
    }
}

// ---------- kernel 5: layer-2 aggregation (warp per recorded edge) ----------
__global__ void k_agg2() {
    int ec = g_e2Count; if (ec > EMAX) ec = EMAX;
    int lane = threadIdx.x & 31;
    int warp = (blockIdx.x * blockDim.x + threadIdx.x) >> 5;
    int nw = (gridDim.x * blockDim.x) >> 5;
    for (int i = warp; i < ec; i += nw) {
        int s = g_e2src[i];
        int ss = g_e2dst[i];
        int ts = g_idxT[s];
        float4 v = ((const float4*)&g_h[(size_t)ts * F])[lane];
        float* dp = &g_agg2[(size_t)ss * F + lane * 4];
        asm volatile("red.global.add.v4.f32 [%0], {%1,%2,%3,%4};"
                     :: "l"(dp), "f"(v.x), "f"(v.y), "f"(v.z), "f"(v.w) : "memory");
    }
}

// ---------- kernel 6: emb = mean2 @ W2l + b2 + h @ W2r at S slots ----------
__global__ void __launch_bounds__(256) k_emb(
                    const float* __restrict__ Wl, const float* __restrict__ Wr,
                    const float* __restrict__ b) {
    extern __shared__ float smem[];
    float* sWl = smem;
    float* sWr = smem + F * F;
    float* stg = smem + 2 * F * F;
    int tid = threadIdx.x;
    {
        const float4* wl4 = (const float4*)Wl;
        const float4* wr4 = (const float4*)Wr;
        float4* sl4 = (float4*)sWl;
        float4* sr4 = (float4*)sWr;
        #pragma unroll
        for (int i = 0; i < (F * F / 4) / 256; i++) {
            sl4[tid + i * 256] = wl4[tid + i * 256];
            sr4[tid + i * 256] = wr4[tid + i * 256];
        }
    }
    __syncthreads();
    int sc = g_sCount; if (sc > SCAP) sc = SCAP;
    int j    = tid & 127;
    int half = tid >> 7;
    for (int tile = blockIdx.x; tile * HTILE < sc; tile += gridDim.x) {
        int g0 = tile * HTILE;
        int nvalid = min(HTILE, sc - g0);
        #pragma unroll
        for (int qi = 0; qi < 4; qi++) {
            int q = half * 4 + qi;
            float mv = 0.0f, hv = 0.0f;
            if (q < nvalid) {
                int ss = g0 + q;
                int node = g_sNodes[ss];
                int ts = g_idxT[node];
                float inv = 1.0f / (float)max(g_cnt2[ss], 1);
                mv = g_agg2[(size_t)ss * F + j] * inv;
                hv = g_h[(size_t)ts * F + j];
            }
            stg[j * 20 + 2 * q]     = mv;
            stg[j * 20 + 2 * q + 1] = hv;
        }
        __syncthreads();
        float a0 = 0.f, a1 = 0.f, a2 = 0.f, a3 = 0.f;
        #pragma unroll 8
        for (int k = 0; k < F; k++) {
            float wl = sWl[k * F + j];
            float wr = sWr[k * F + j];
            const float4* row = (const float4*)&stg[k * 20 + half * 8];
            float4 v0 = row[0];
            float4 v1 = row[1];
            a0 += v0.x * wl + v0.y * wr;
            a1 += v0.z * wl + v0.w * wr;
            a2 += v1.x * wl + v1.y * wr;
            a3 += v1.z * wl + v1.w * wr;
        }
        float bb = b[j];
        float acc[4] = {a0, a1, a2, a3};
        #pragma unroll
        for (int qi = 0; qi < 4; qi++) {
            int q = half * 4 + qi;
            if (q < nvalid)
                g_emb[(size_t)(g0 + q) * F + j] = acc[qi] + bb;
        }
        __syncthreads();
    }
}

// ---------- kernel 7: MLP head (block per neighbor), Wlin1 smem-resident ----------
__global__ void __launch_bounds__(128) k_head2(
                       const void* nbrs, const void* curr_p, const void* dest_p,
                       const float* __restrict__ W1, const float* __restrict__ b1,
                       const float* __restrict__ W2, const float* __restrict__ bo,
                       float* __restrict__ out) {
    extern __shared__ float smem[];
    float* sW1 = smem;                   // 3F*F floats
    __shared__ float cat[3 * F];
    __shared__ float red[F];
    int j = threadIdx.x;
    {
        const float4* w4 = (const float4*)W1;
        float4* s4 = (float4*)sW1;
        #pragma unroll
        for (int i = 0; i < (3 * F * F / 4) / 128; i++)
            s4[j + i * 128] = w4[j + i * 128];
    }
    int k = blockIdx.x;
    int curr = read_scalar_idx(curr_p);
    int dest = read_scalar_idx(dest_p);
    int nb = g_nbr64 ? (int)((const long long*)nbrs)[k] : ((const int*)nbrs)[k];
    cat[j]         = g_emb[(size_t)g_idxS[curr] * F + j];
    cat[F + j]     = g_emb[(size_t)g_idxS[dest] * F + j];
    cat[2 * F + j] = g_emb[(size_t)g_idxS[nb] * F + j];
    __syncthreads();
    float acc = 0.0f;
    #pragma unroll 8
    for (int c = 0; c < 3 * F; c++)
        acc += cat[c] * sW1[c * F + j];
    float hid = fmaxf(acc + b1[j], 0.0f);
    red[j] = hid * W2[j];
    __syncthreads();
    for (int st = 64; st > 0; st >>= 1) {
        if (j < st) red[j] += red[j + st];
        __syncthreads();
    }
    if (j == 0) out[k] = red[0] + bo[0];
}

// ---------------- launch ----------------
extern "C" void kernel_launch(void* const* d_in, const int* in_sizes, int n_in,
                              void* d_out, int out_size) {
    const float* x    = (const float*)d_in[0];
    const void*  edges= d_in[1];
    const void*  curr = d_in[2];
    const void*  dest = d_in[3];
    const void*  nbrs = d_in[4];
    const float* W1l  = (const float*)d_in[5];
    const float* W1r  = (const float*)d_in[6];
    const float* b1   = (const float*)d_in[7];
    const float* W2l  = (const float*)d_in[8];
    const float* W2r  = (const float*)d_in[9];
    const float* b2   = (const float*)d_in[10];
    const float* Wl1  = (const float*)d_in[11];
    const float* bl1  = (const float*)d_in[12];
    const float* Wl2  = (const float*)d_in[13];
    const float* bl2  = (const float*)d_in[14];
    float* out = (float*)d_out;

    cudaFuncSetAttribute(k_h,     cudaFuncAttributeMaxDynamicSharedMemorySize, SMEM_H);
    cudaFuncSetAttribute(k_emb,   cudaFuncAttributeMaxDynamicSharedMemorySize, SMEM_EMB);
    cudaFuncSetAttribute(k_head2, cudaFuncAttributeMaxDynamicSharedMemorySize, SMEM_HEAD);

    long long E = (long long)(in_sizes[1] / 2);
    int eb4 = (int)((E + 1023) / 1024);   // 4 edges per thread, 256 threads

    k_prepS<<<1, 128>>>(edges, nbrs, curr, dest, E);
    k_scan1<<<eb4, 256>>>(edges, E);
    k_scan2<<<eb4, 256>>>(edges, x, E);
    k_h<<<148, 512, SMEM_H>>>(x, W1l, W1r, b1);
    k_agg2<<<96, 256>>>();
    k_emb<<<10, 256, SMEM_EMB>>>(W2l, W2r, b2);
    k_head2<<<KNBR, 128, SMEM_HEAD>>>(nbrs, curr, dest, Wl1, bl1, Wl2, bl2, out);
}

// round 17
// speedup vs baseline: 1.0663x; 1.0663x over previous
#include <cuda_runtime.h>
#include <stdint.h>
#include <string.h>

#define NN      100000
#define F       128
#define KNBR    64
#define SCAP    80
#define TCAP    4096
#define EMAX    3300000
#define NWORDS  ((NN + 31) / 32)
#define TILE16  16
#define HTILE   8

// dynamic smem sizes (bytes)
#define SMEM_H    (2 * F * F * 4 + F * 36 * 4)   // k_h: interleaved W + staging
#define SMEM_EMB  (2 * F * F * 4 + F * 20 * 4)   // k_emb: Wl + Wr + staging
#define SMEM_HEAD (3 * F * F * 4)                 // k_head2: Wlin1

// PDL primitive (sm_90+)
__device__ __forceinline__ void gdc_wait() {
    asm volatile("griddepcontrol.wait;" ::: "memory");
}

// ---------------- static scratch (no allocations allowed) ----------------
__device__ unsigned g_bitS[NWORDS];
__device__ unsigned g_bitT[NWORDS];
__device__ int   g_idxS[NN];
__device__ int   g_idxT[NN];
__device__ int   g_sNodes[SCAP];
__device__ int   g_tNodes[TCAP];
__device__ int   g_sCount;
__device__ int   g_tCount;
__device__ int   g_e2Count;
__device__ int   g_edge64;
__device__ int   g_nbr64;
__device__ int   g_e2src[EMAX];
__device__ int   g_e2dst[EMAX];
__device__ float g_agg1[(size_t)TCAP * F];
__device__ int   g_cnt1[TCAP];
__device__ float g_h[(size_t)TCAP * F];
__device__ float g_agg2[SCAP * F];
__device__ int   g_cnt2[SCAP];
__device__ float g_emb[SCAP * F];

__device__ __forceinline__ int read_scalar_idx(const void* p) {
    int v = *(const int*)p;
    if (v >= 0 && v < NN) return v;
    float f = *(const float*)p;
    return (int)f;
}

__device__ __forceinline__ void claimT(int node) {
    unsigned m = 1u << (node & 31);
    unsigned old = atomicOr(&g_bitT[node >> 5], m);
    if (!(old & m)) {
        int ts = atomicAdd(&g_tCount, 1);
        if (ts < TCAP) { g_tNodes[ts] = node; g_idxT[node] = ts; }
        else g_idxT[node] = 0;
    }
}

// ---------- kernel 1 (1 block): bitmaps + counters + dtype probes + build S ----------
__global__ void k_prepS(const void* edges, const void* nbrs,
                        const void* curr_p, const void* dest_p, long long E) {
    int t = threadIdx.x;
    for (int i = t; i < NWORDS; i += blockDim.x) { g_bitS[i] = 0u; g_bitT[i] = 0u; }
    if (t == 0) {
        g_sCount = 0; g_tCount = 0; g_e2Count = 0;
        const long long* e64 = (const long long*)edges;
        int n = (int)(2 * E < 8 ? 2 * E : 8);
        int ok = 1;
        for (int q = 0; q < n; q++) {
            long long v = e64[q];
            if (v < 0 || v >= NN) ok = 0;
        }
        g_edge64 = ok;
        const long long* n64 = (const long long*)nbrs;
        ok = 1;
        for (int q = 0; q < 8; q++) {
            long long v = n64[q];
            if (v < 0 || v >= NN) ok = 0;
        }
        g_nbr64 = ok;
    }
    __syncthreads();
    if (t < KNBR + 2) {
        int node;
        if (t == 0)      node = read_scalar_idx(curr_p);
        else if (t == 1) node = read_scalar_idx(dest_p);
        else node = g_nbr64 ? (int)((const long long*)nbrs)[t - 2]
                            : ((const int*)nbrs)[t - 2];
        if (node >= 0 && node < NN) {
            unsigned m = 1u << (node & 31);
            unsigned old = atomicOr(&g_bitS[node >> 5], m);
            if (!(old & m)) {
                int s = atomicAdd(&g_sCount, 1);
                if (s < SCAP) { g_sNodes[s] = node; g_idxS[node] = s; }
            }
            claimT(node);
        }
    }
}

// ---------- kernel 2 (PDL): zero accum (disjoint from prepS) -> wait -> scan dst in S ----------
__global__ void k_scan1(const void* __restrict__ edges, long long E) {
    {
        long long gt = (long long)blockIdx.x * blockDim.x + threadIdx.x;
        long long gs = (long long)gridDim.x * blockDim.x;
        for (long long i = gt; i < (long long)TCAP * F; i += gs) g_agg1[i] = 0.0f;
        for (long long i = gt; i < TCAP; i += gs) g_cnt1[i] = 0;
        for (long long i = gt; i < SCAP * F; i += gs) g_agg2[i] = 0.0f;
        if (gt < SCAP) g_cnt2[gt] = 0;
    }
    gdc_wait();   // bitS/idxS/edge64 from prepS now visible
    long long base = ((long long)blockIdx.x * blockDim.x + threadIdx.x) * 4;
    if (base >= E) return;
    int is64 = g_edge64;
    int nv = (int)(E - base < 4 ? E - base : 4);
    bool vec = (nv == 4);
    int d[4];
    if (is64) {
        const long long* __restrict__ p = (const long long*)edges + E + base;
        if (vec) {
            longlong2 v0 = *(const longlong2*)p;
            longlong2 v1 = *(const longlong2*)(p + 2);
            d[0] = (int)v0.x; d[1] = (int)v0.y; d[2] = (int)v1.x; d[3] = (int)v1.y;
        } else {
            #pragma unroll
            for (int q = 0; q < 4; q++) d[q] = (q < nv) ? (int)p[q] : -1;
        }
    } else {
        const int* __restrict__ p = (const int*)edges + E + base;
        if (vec) {
            int4 v = *(const int4*)p;
            d[0] = v.x; d[1] = v.y; d[2] = v.z; d[3] = v.w;
        } else {
            #pragma unroll
            for (int q = 0; q < 4; q++) d[q] = (q < nv) ? p[q] : -1;
        }
    }
    #pragma unroll
    for (int q = 0; q < 4; q++) {
        int dd = d[q];
        if ((unsigned)dd < NN && (g_bitS[dd >> 5] & (1u << (dd & 31)))) {
            int ss = g_idxS[dd];
            int s = is64 ? (int)((const long long*)edges)[base + q]
                         : ((const int*)edges)[base + q];
            if ((unsigned)s >= NN) continue;
            atomicAdd(&g_cnt2[ss], 1);
            int pos = atomicAdd(&g_e2Count, 1);
            if (pos < EMAX) { g_e2src[pos] = s; g_e2dst[pos] = ss; }
            claimT(s);
        }
    }
}

// ---------- kernel 3 (PDL): wait -> scan edges (4/thread), dst in T -> accumulate x ----------
__global__ void k_scan2(const void* __restrict__ edges, const float* __restrict__ x,
                        long long E) {
    gdc_wait();   // bitT/idxT/cnt1/edge64 + zeroed agg1 from scan1 now visible
    long long base = ((long long)blockIdx.x * blockDim.x + threadIdx.x) * 4;
    int lane = threadIdx.x & 31;
    int is64 = g_edge64;
    int d[4] = {-1, -1, -1, -1};
    if (base < E) {
        int nv = (int)(E - base < 4 ? E - base : 4);
        bool vec = (nv == 4);
        if (is64) {
            const long long* __restrict__ p = (const long long*)edges + E + base;
            if (vec) {
                longlong2 v0 = *(const longlong2*)p;
                longlong2 v1 = *(const longlong2*)(p + 2);
                d[0] = (int)v0.x; d[1] = (int)v0.y; d[2] = (int)v1.x; d[3] = (int)v1.y;
            } else {
                #pragma unroll
                for (int q = 0; q < 4; q++) if (q < nv) d[q] = (int)p[q];
            }
        } else {
            const int* __restrict__ p = (const int*)edges + E + base;
            if (vec) {
                int4 v = *(const int4*)p;
                d[0] = v.x; d[1] = v.y; d[2] = v.z; d[3] = v.w;
            } else {
                #pragma unroll
                for (int q = 0; q < 4; q++) if (q < nv) d[q] = p[q];
            }
        }
    }
    int s[4], ts[4];
    bool act[4];
    #pragma unroll
    for (int q = 0; q < 4; q++) {
        act[q] = false;
        s[q] = 0; ts[q] = 0;
        int dd = d[q];
        if ((unsigned)dd < NN && (g_bitT[dd >> 5] & (1u << (dd & 31)))) {
            ts[q] = g_idxT[dd];
            int sv = is64 ? (int)((const long long*)edges)[base + q]
                          : ((const int*)edges)[base + q];
            if ((unsigned)sv < NN) {
                s[q] = sv;
                atomicAdd(&g_cnt1[ts[q]], 1);
                act[q] = true;
            }
        }
    }
    #pragma unroll
    for (int q = 0; q < 4; q++) {
        unsigned m = __ballot_sync(0xffffffffu, act[q]);
        while (m) {
            int l = __ffs(m) - 1;
            m &= m - 1;
            int ls = __shfl_sync(0xffffffffu, s[q], l);
            int lt = __shfl_sync(0xffffffffu, ts[q], l);
            float4 v = ((const float4*)(x + (size_t)ls * F))[lane];
            float* dp = &g_agg1[(size_t)lt * F + lane * 4];
            asm volatile("red.global.add.v4.f32 [%0], {%1,%2,%3,%4};"
                         :: "l"(dp), "f"(v.x), "f"(v.y), "f"(v.z), "f"(v.w) : "memory");
        }
    }
}

// ---------- kernel 4 (PDL): stage W (const input) -> wait -> h GEMM, 16-node tiles ----------
__global__ void __launch_bounds__(512) k_h(
                    const float* __restrict__ x,
                    const float* __restrict__ Wl, const float* __restrict__ Wr,
                    const float* __restrict__ b) {
    extern __shared__ float smem[];
    float* sW  = smem;                  // 2*F*F interleaved {wl,wr}
    float* stg = smem + 2 * F * F;      // F*36
    int tid = threadIdx.x;
    // stage weights: pure const inputs, overlaps scan2 tail
    {
        const float4* wl4 = (const float4*)Wl;
        const float4* wr4 = (const float4*)Wr;
        float2* sW2 = (float2*)sW;
        #pragma unroll
        for (int i = tid; i < F * F / 4; i += 512) {
            float4 a = wl4[i];
            float4 c = wr4[i];
            sW2[4 * i + 0] = make_float2(a.x, c.x);
            sW2[4 * i + 1] = make_float2(a.y, c.y);
            sW2[4 * i + 2] = make_float2(a.z, c.z);
            sW2[4 * i + 3] = make_float2(a.w, c.w);
        }
    }
    gdc_wait();   // agg1/cnt1/tCount/tNodes from scans now visible
    __syncthreads();
    int tc = g_tCount; if (tc > TCAP) tc = TCAP;
    int ntiles = (tc + TILE16 - 1) / TILE16;
    if ((int)blockIdx.x >= ntiles) return;
    int j       = tid & 127;
    int quarter = tid >> 7;
    for (int tile = blockIdx.x; tile < ntiles; tile += gridDim.x) {
        int g0 = tile * TILE16;
        int nvalid = min(TILE16, tc - g0);
        #pragma unroll
        for (int qi = 0; qi < 4; qi++) {
            int q = quarter * 4 + qi;
            float mv = 0.0f, xv = 0.0f;
            if (q < nvalid) {
                int t = g0 + q;
                int node = g_tNodes[t];
                float inv = 1.0f / (float)max(g_cnt1[t], 1);
                mv = g_agg1[(size_t)t * F + j] * inv;
                xv = x[(size_t)node * F + j];
            }
            stg[j * 36 + 2 * q]     = mv;
            stg[j * 36 + 2 * q + 1] = xv;
        }
        __syncthreads();
        float a0 = 0.f, a1 = 0.f, a2 = 0.f, a3 = 0.f;
        #pragma unroll 8
        for (int k = 0; k < F; k++) {
            float2 w = ((const float2*)&sW[k * 256])[j];
            const float4* row = (const float4*)&stg[k * 36 + quarter * 8];
            float4 v0 = row[0];
            float4 v1 = row[1];
            a0 += v0.x * w.x + v0.y * w.y;
            a1 += v0.z * w.x + v0.w * w.y;
            a2 += v1.x * w.x + v1.y * w.y;
            a3 += v1.z * w.x + v1.w * w.y;
        }
        float bb = b[j];
        float acc[4] = {a0, a1, a2, a3};
        #pragma unroll
        for (int qi = 0; qi < 4; qi++) {
            int q = quarter * 4 + qi;
            if (q < nvalid)
                g_h[(size_t)(g0 + q) * F + j] = fmaxf(acc[qi] + bb, 0.0f);
        }
        __syncthreads();
    }
}

// ---------- kernel 5: layer-2 aggregation (warp per recorded edge) ----------
__global__ void k_agg2() {
    int ec = g_e2Count; if (ec > EMAX) ec = EMAX;
    int lane = threadIdx.x & 31;
    int warp = (blockIdx.x * blockDim.x + threadIdx.x) >> 5;
    int nw = (gridDim.x * blockDim.x) >> 5;
    for (int i = warp; i < ec; i += nw) {
        int s = g_e2src[i];
        int ss = g_e2dst[i];
        int ts = g_idxT[s];
        float4 v = ((const float4*)&g_h[(size_t)ts * F])[lane];
        float* dp = &g_agg2[(size_t)ss * F + lane * 4];
        asm volatile("red.global.add.v4.f32 [%0], {%1,%2,%3,%4};"
                     :: "l"(dp), "f"(v.x), "f"(v.y), "f"(v.z), "f"(v.w) : "memory");
    }
}

// ---------- kernel 6 (PDL): stage W -> wait -> emb GEMM at S slots ----------
__global__ void __launch_bounds__(256) k_emb(
                    const float* __restrict__ Wl, const float* __restrict__ Wr,
                    const float* __restrict__ b) {
    extern __shared__ float smem[];
    float* sWl = smem;
    float* sWr = smem + F * F;
    float* stg = smem + 2 * F * F;
    int tid = threadIdx.x;
    {
        const float4* wl4 = (const float4*)Wl;
        const float4* wr4 = (const float4*)Wr;
        float4* sl4 = (float4*)sWl;
        float4* sr4 = (float4*)sWr;
        #pragma unroll
        for (int i = 0; i < (F * F / 4) / 256; i++) {
            sl4[tid + i * 256] = wl4[tid + i * 256];
            sr4[tid + i * 256] = wr4[tid + i * 256];
        }
    }
    gdc_wait();   // agg2/cnt2/h from agg2/k_h now visible
    __syncthreads();
    int sc = g_sCount; if (sc > SCAP) sc = SCAP;
    int j    = tid & 127;
    int half = tid >> 7;
    for (int tile = blockIdx.x; tile * HTILE < sc; tile += gridDim.x) {
        int g0 = tile * HTILE;
        int nvalid = min(HTILE, sc - g0);
        #pragma unroll
        for (int qi = 0; qi < 4; qi++) {
            int q = half * 4 + qi;
            float mv = 0.0f, hv = 0.0f;
            if (q < nvalid) {
                int ss = g0 + q;
                int node = g_sNodes[ss];
                int ts = g_idxT[node];
                float inv = 1.0f / (float)max(g_cnt2[ss], 1);
                mv = g_agg2[(size_t)ss * F + j] * inv;
                hv = g_h[(size_t)ts * F + j];
            }
            stg[j * 20 + 2 * q]     = mv;
            stg[j * 20 + 2 * q + 1] = hv;
        }
        __syncthreads();
        float a0 = 0.f, a1 = 0.f, a2 = 0.f, a3 = 0.f;
        #pragma unroll 8
        for (int k = 0; k < F; k++) {
            float wl = sWl[k * F + j];
            float wr = sWr[k * F + j];
            const float4* row = (const float4*)&stg[k * 20 + half * 8];
            float4 v0 = row[0];
            float4 v1 = row[1];
            a0 += v0.x * wl + v0.y * wr;
            a1 += v0.z * wl + v0.w * wr;
            a2 += v1.x * wl + v1.y * wr;
            a3 += v1.z * wl + v1.w * wr;
        }
        float bb = b[j];
        float acc[4] = {a0, a1, a2, a3};
        #pragma unroll
        for (int qi = 0; qi < 4; qi++) {
            int q = half * 4 + qi;
            if (q < nvalid)
                g_emb[(size_t)(g0 + q) * F + j] = acc[qi] + bb;
        }
        __syncthreads();
    }
}

// ---------- kernel 7 (PDL): stage Wlin1 -> wait -> MLP head ----------
__global__ void __launch_bounds__(128) k_head2(
                       const void* nbrs, const void* curr_p, const void* dest_p,
                       const float* __restrict__ W1, const float* __restrict__ b1,
                       const float* __restrict__ W2, const float* __restrict__ bo,
                       float* __restrict__ out) {
    extern __shared__ float smem[];
    float* sW1 = smem;                   // 3F*F floats
    __shared__ float cat[3 * F];
    __shared__ float red[F];
    int j = threadIdx.x;
    {
        const float4* w4 = (const float4*)W1;
        float4* s4 = (float4*)sW1;
        #pragma unroll
        for (int i = 0; i < (3 * F * F / 4) / 128; i++)
            s4[j + i * 128] = w4[j + i * 128];
    }
    gdc_wait();   // g_emb from k_emb now visible
    int k = blockIdx.x;
    int curr = read_scalar_idx(curr_p);
    int dest = read_scalar_idx(dest_p);
    int nb = g_nbr64 ? (int)((const long long*)nbrs)[k] : ((const int*)nbrs)[k];
    cat[j]         = g_emb[(size_t)g_idxS[curr] * F + j];
    cat[F + j]     = g_emb[(size_t)g_idxS[dest] * F + j];
    cat[2 * F + j] = g_emb[(size_t)g_idxS[nb] * F + j];
    __syncthreads();
    float acc = 0.0f;
    #pragma unroll 8
    for (int c = 0; c < 3 * F; c++)
        acc += cat[c] * sW1[c * F + j];
    float hid = fmaxf(acc + b1[j], 0.0f);
    red[j] = hid * W2[j];
    __syncthreads();
    for (int st = 64; st > 0; st >>= 1) {
        if (j < st) red[j] += red[j + st];
        __syncthreads();
    }
    if (j == 0) out[k] = red[0] + bo[0];
}

// ---------------- launch ----------------
static void launch_pdl(const void* func, dim3 grid, dim3 block, size_t smem, void** args) {
    cudaLaunchConfig_t cfg;
    memset(&cfg, 0, sizeof(cfg));
    cfg.gridDim = grid;
    cfg.blockDim = block;
    cfg.dynamicSmemBytes = smem;
    cfg.stream = 0;
    cudaLaunchAttribute attr;
    attr.id = cudaLaunchAttributeProgrammaticStreamSerialization;
    attr.val.programmaticStreamSerializationAllowed = 1;
    cfg.attrs = &attr;
    cfg.numAttrs = 1;
    cudaLaunchKernelExC(&cfg, func, args);
}

extern "C" void kernel_launch(void* const* d_in, const int* in_sizes, int n_in,
                              void* d_out, int out_size) {
    const float* x    = (const float*)d_in[0];
    const void*  edges= d_in[1];
    const void*  curr = d_in[2];
    const void*  dest = d_in[3];
    const void*  nbrs = d_in[4];
    const float* W1l  = (const float*)d_in[5];
    const float* W1r  = (const float*)d_in[6];
    const float* b1   = (const float*)d_in[7];
    const float* W2l  = (const float*)d_in[8];
    const float* W2r  = (const float*)d_in[9];
    const float* b2   = (const float*)d_in[10];
    const float* Wl1  = (const float*)d_in[11];
    const float* bl1  = (const float*)d_in[12];
    const float* Wl2  = (const float*)d_in[13];
    const float* bl2  = (const float*)d_in[14];
    float* out = (float*)d_out;

    cudaFuncSetAttribute(k_h,     cudaFuncAttributeMaxDynamicSharedMemorySize, SMEM_H);
    cudaFuncSetAttribute(k_emb,   cudaFuncAttributeMaxDynamicSharedMemorySize, SMEM_EMB);
    cudaFuncSetAttribute(k_head2, cudaFuncAttributeMaxDynamicSharedMemorySize, SMEM_HEAD);

    long long E = (long long)(in_sizes[1] / 2);
    int eb4 = (int)((E + 1023) / 1024);   // 4 edges per thread, 256 threads

    k_prepS<<<1, 128>>>(edges, nbrs, curr, dest, E);

    {
        void* args[] = {(void*)&edges, (void*)&E};
        launch_pdl((const void*)k_scan1, dim3(eb4), dim3(256), 0, args);
    }
    {
        void* args[] = {(void*)&edges, (void*)&x, (void*)&E};
        launch_pdl((const void*)k_scan2, dim3(eb4), dim3(256), 0, args);
    }
    {
        void* args[] = {(void*)&x, (void*)&W1l, (void*)&W1r, (void*)&b1};
        launch_pdl((const void*)k_h, dim3(148), dim3(512), SMEM_H, args);
    }
    k_agg2<<<96, 256>>>();
    {
        void* args[] = {(void*)&W2l, (void*)&W2r, (void*)&b2};
        launch_pdl((const void*)k_emb, dim3(10), dim3(256), SMEM_EMB, args);
    }
    {
        void* args[] = {(void*)&nbrs, (void*)&curr, (void*)&dest,
                        (void*)&Wl1, (void*)&bl1, (void*)&Wl2, (void*)&bl2, (void*)&out};
        launch_pdl((const void*)k_head2, dim3(KNBR), dim3(128), SMEM_HEAD, args);
    }
}